// round 8
// baseline (speedup 1.0000x reference)
#include <cuda_runtime.h>
#include <cuda_fp16.h>
#include <cstdint>

#define NUM_USERS 100000
#define NUM_ITEMS 200000
#define N_TOTAL   300000
#define EMBED_DIM 64
#define NNZ       4000000
#define BATCH     16384

#define SCAN_B 1024
#define NB_SCAN ((N_TOTAL + SCAN_B - 1) / SCAN_B)   // 293

// Node features fp16: 64 halves = 8 uint4 per row. 38.4MB per buffer.
// [0]=x0, [1]=x1, [2]=x2, [3]=s = x0+x1+x2
__device__ uint4 g_xh[4][(size_t)N_TOTAL * 8];
// CSR build scratch. Zero-initialized at module load; scan_local re-zeroes
// g_cnt every replay (self-cleaning), g_cur is fully overwritten by scan_add2.
__device__ int  g_cnt[N_TOTAL];
__device__ int  g_off[N_TOTAL + 1];
__device__ int  g_cur[N_TOTAL];          // pre-biased cursor: g_cur[r] = off[r]
__device__ int  g_bsum[NB_SCAN];
__device__ int  g_rank[NNZ];             // per-edge rank within its dest row
// Row-sorted packed edges: (col, val_bits). 32MB.
__device__ int2 g_edges[NNZ];

// ---------------------------------------------------------------------------
// hist + rank + init fused:
//   idx < NNZ        : rank[e] = atomicAdd(cnt[row[e]], 1)  (reuse the return
//                      value the plain histogram discards)
//   idx < N_TOTAL*8  : x0[idx] = fp16(concat(user_emb, item_emb))
// ---------------------------------------------------------------------------
__global__ void hist_init_kernel(const int*    __restrict__ rows,
                                 const float4* __restrict__ uw,
                                 const float4* __restrict__ iw) {
    int idx = blockIdx.x * blockDim.x + threadIdx.x;
    if (idx < NNZ) {
        g_rank[idx] = atomicAdd(&g_cnt[__ldg(rows + idx)], 1);
    }
    if (idx < N_TOTAL * 8) {
        int row = idx >> 3;
        int c   = idx & 7;
        const float4* s = (row < NUM_USERS)
            ? (uw + (size_t)row * 16 + c * 2)
            : (iw + (size_t)(row - NUM_USERS) * 16 + c * 2);
        float4 f0 = __ldg(s);
        float4 f1 = __ldg(s + 1);
        uint4 o;
        __half2* oh = reinterpret_cast<__half2*>(&o);
        oh[0] = __float22half2_rn(make_float2(f0.x, f0.y));
        oh[1] = __float22half2_rn(make_float2(f0.z, f0.w));
        oh[2] = __float22half2_rn(make_float2(f1.x, f1.y));
        oh[3] = __float22half2_rn(make_float2(f1.z, f1.w));
        g_xh[0][idx] = o;
    }
}

// ---------------------------------------------------------------------------
// scan step 1: per-block inclusive scan of g_cnt, publish block sums.
// Also RESETS g_cnt to zero (self-cleaning for the next graph replay).
// ---------------------------------------------------------------------------
__global__ void scan_local_kernel() {
    __shared__ int sh[SCAN_B];
    int gid = blockIdx.x * SCAN_B + threadIdx.x;
    int v = 0;
    if (gid < N_TOTAL) {
        v = g_cnt[gid];
        g_cnt[gid] = 0;
    }
    sh[threadIdx.x] = v;
    __syncthreads();
    #pragma unroll
    for (int o = 1; o < SCAN_B; o <<= 1) {
        int t = (threadIdx.x >= o) ? sh[threadIdx.x - o] : 0;
        __syncthreads();
        sh[threadIdx.x] += t;
        __syncthreads();
    }
    if (gid < N_TOTAL) g_off[gid + 1] = sh[threadIdx.x];
    if (threadIdx.x == SCAN_B - 1) g_bsum[blockIdx.x] = sh[threadIdx.x];
}

// ---------------------------------------------------------------------------
// scan step 2: every block redundantly scans the 293 block sums in smem,
// adds its exclusive block prefix to its g_off range, AND writes the final
// exclusive prefix into g_cur (pos base for the atomic-free scatter).
// ---------------------------------------------------------------------------
__global__ void scan_add2_kernel() {
    __shared__ int sh[SCAN_B];
    int t = threadIdx.x;
    sh[t] = (t < NB_SCAN) ? g_bsum[t] : 0;
    __syncthreads();
    #pragma unroll
    for (int o = 1; o < SCAN_B; o <<= 1) {
        int v = (t >= o) ? sh[t - o] : 0;
        __syncthreads();
        sh[t] += v;
        __syncthreads();
    }
    int prev = (blockIdx.x > 0) ? sh[blockIdx.x - 1] : 0;

    int gid = blockIdx.x * SCAN_B + t;

    // raw local-inclusive value of element gid-1 (same block only; written by
    // scan_local). Read BEFORE the in-place += below (sync-guarded).
    int raw = 0;
    if (t > 0 && gid <= N_TOTAL) raw = g_off[gid];
    __syncthreads();

    if (gid == 0) g_off[0] = 0;
    if (gid < N_TOTAL) {
        g_off[gid + 1] += prev;
        g_cur[gid] = (t == 0) ? prev : (raw + prev);
    }
}

// ---------------------------------------------------------------------------
// scatter (atomic-free): pos = off[row] + precomputed rank. The only random
// access is a plain 4B load of g_cur[r] (~13 edges/row share its sector).
// ---------------------------------------------------------------------------
__global__ void scatter_kernel(const int*   __restrict__ rows,
                               const int*   __restrict__ cols,
                               const float* __restrict__ vals) {
    int e = blockIdx.x * blockDim.x + threadIdx.x;
    if (e >= NNZ) return;
    int r    = __ldg(rows + e);
    int pos  = __ldg(&g_cur[r]) + __ldg(&g_rank[e]);
    g_edges[pos] = make_int2(__ldg(cols + e),
                             __float_as_int(__ldg(vals + e)));
}

// ---------------------------------------------------------------------------
// fp16 CSR spmm: 8 lanes per destination row, lane c handles dims [8c,8c+8).
// 4-edge unroll for memory-level parallelism on the random gathers.
// FUSE_SUM: also write s = x0[row] + x1[row] + acc (on the x1->x2 pass)
// ---------------------------------------------------------------------------
__device__ __forceinline__ void acc8(float2& a0, float2& a1,
                                     float2& a2, float2& a3,
                                     uint4 u, float v) {
    const __half2* h = reinterpret_cast<const __half2*>(&u);
    float2 f;
    f = __half22float2(h[0]); a0.x += v * f.x; a0.y += v * f.y;
    f = __half22float2(h[1]); a1.x += v * f.x; a1.y += v * f.y;
    f = __half22float2(h[2]); a2.x += v * f.x; a2.y += v * f.y;
    f = __half22float2(h[3]); a3.x += v * f.x; a3.y += v * f.y;
}

__device__ __forceinline__ void add8(float2& a0, float2& a1,
                                     float2& a2, float2& a3, uint4 u) {
    const __half2* h = reinterpret_cast<const __half2*>(&u);
    float2 f;
    f = __half22float2(h[0]); a0.x += f.x; a0.y += f.y;
    f = __half22float2(h[1]); a1.x += f.x; a1.y += f.y;
    f = __half22float2(h[2]); a2.x += f.x; a2.y += f.y;
    f = __half22float2(h[3]); a3.x += f.x; a3.y += f.y;
}

__device__ __forceinline__ uint4 pack8(float2 a0, float2 a1,
                                       float2 a2, float2 a3) {
    uint4 o;
    __half2* oh = reinterpret_cast<__half2*>(&o);
    oh[0] = __float22half2_rn(a0);
    oh[1] = __float22half2_rn(a1);
    oh[2] = __float22half2_rn(a2);
    oh[3] = __float22half2_rn(a3);
    return o;
}

template <bool FUSE_SUM>
__global__ void spmm_csr_kernel(int src_l, int dst_l) {
    int tid = blockIdx.x * blockDim.x + threadIdx.x;
    int row = tid >> 3;
    int c   = tid & 7;
    if (row >= N_TOTAL) return;

    const uint4* __restrict__ src = g_xh[src_l];
    uint4*       __restrict__ dst = g_xh[dst_l];

    int beg = __ldg(&g_off[row]);
    int end = __ldg(&g_off[row + 1]);

    float2 a0 = {0.f, 0.f}, a1 = {0.f, 0.f}, a2 = {0.f, 0.f}, a3 = {0.f, 0.f};
    int e = beg;
    for (; e + 3 < end; e += 4) {
        int2 p0 = __ldg(&g_edges[e]);
        int2 p1 = __ldg(&g_edges[e + 1]);
        int2 p2 = __ldg(&g_edges[e + 2]);
        int2 p3 = __ldg(&g_edges[e + 3]);
        uint4 u0 = __ldg(src + ((size_t)p0.x * 8 + c));
        uint4 u1 = __ldg(src + ((size_t)p1.x * 8 + c));
        uint4 u2 = __ldg(src + ((size_t)p2.x * 8 + c));
        uint4 u3 = __ldg(src + ((size_t)p3.x * 8 + c));
        acc8(a0, a1, a2, a3, u0, __int_as_float(p0.y));
        acc8(a0, a1, a2, a3, u1, __int_as_float(p1.y));
        acc8(a0, a1, a2, a3, u2, __int_as_float(p2.y));
        acc8(a0, a1, a2, a3, u3, __int_as_float(p3.y));
    }
    for (; e < end; e++) {
        int2 p = __ldg(&g_edges[e]);
        uint4 u = __ldg(src + ((size_t)p.x * 8 + c));
        acc8(a0, a1, a2, a3, u, __int_as_float(p.y));
    }

    size_t oidx = (size_t)row * 8 + c;
    __stcs(dst + oidx, pack8(a0, a1, a2, a3));

    if (FUSE_SUM) {
        // s = x0 + x1 + x2 ; src here is x1
        add8(a0, a1, a2, a3, __ldg(&g_xh[0][oidx]));
        add8(a0, a1, a2, a3, __ldg(src + oidx));
        __stcs(&g_xh[3][oidx], pack8(a0, a1, a2, a3));
    }
}

// ---------------------------------------------------------------------------
// final: per batch element, compute layer-3 rows u and i on the fly from x2,
// add s, dot, scale. 8 lanes per batch element; lane c owns dims [8c, 8c+8).
// ---------------------------------------------------------------------------
__global__ void final_kernel(const int* __restrict__ uid,
                             const int* __restrict__ iid,
                             float* __restrict__ out) {
    int tid = blockIdx.x * blockDim.x + threadIdx.x;
    if (tid >= BATCH * 8) return;
    int b = tid >> 3;
    int c = tid & 7;

    int ru = __ldg(uid + b);
    int ri = __ldg(iid + b) + NUM_USERS;

    const uint4* __restrict__ x2 = g_xh[2];

    float fu[8], fi[8];
    {   // s rows
        uint4 su = __ldg(&g_xh[3][(size_t)ru * 8 + c]);
        uint4 si = __ldg(&g_xh[3][(size_t)ri * 8 + c]);
        const __half2* hu = reinterpret_cast<const __half2*>(&su);
        const __half2* hi = reinterpret_cast<const __half2*>(&si);
        #pragma unroll
        for (int k = 0; k < 4; k++) {
            float2 f = __half22float2(hu[k]);
            fu[2 * k] = f.x; fu[2 * k + 1] = f.y;
            f = __half22float2(hi[k]);
            fi[2 * k] = f.x; fi[2 * k + 1] = f.y;
        }
    }

    // layer-3 row u
    {
        int beg = __ldg(&g_off[ru]);
        int end = __ldg(&g_off[ru + 1]);
        for (int e = beg; e < end; e++) {
            int2 p = __ldg(&g_edges[e]);
            uint4 u = __ldg(x2 + ((size_t)p.x * 8 + c));
            float v = __int_as_float(p.y);
            const __half2* h = reinterpret_cast<const __half2*>(&u);
            #pragma unroll
            for (int k = 0; k < 4; k++) {
                float2 f = __half22float2(h[k]);
                fu[2 * k]     += v * f.x;
                fu[2 * k + 1] += v * f.y;
            }
        }
    }
    // layer-3 row i
    {
        int beg = __ldg(&g_off[ri]);
        int end = __ldg(&g_off[ri + 1]);
        for (int e = beg; e < end; e++) {
            int2 p = __ldg(&g_edges[e]);
            uint4 u = __ldg(x2 + ((size_t)p.x * 8 + c));
            float v = __int_as_float(p.y);
            const __half2* h = reinterpret_cast<const __half2*>(&u);
            #pragma unroll
            for (int k = 0; k < 4; k++) {
                float2 f = __half22float2(h[k]);
                fi[2 * k]     += v * f.x;
                fi[2 * k + 1] += v * f.y;
            }
        }
    }

    float s = 0.f;
    #pragma unroll
    for (int k = 0; k < 8; k++) s += fu[k] * fi[k];

    #pragma unroll
    for (int o = 4; o > 0; o >>= 1)
        s += __shfl_down_sync(0xffffffffu, s, o, 8);

    if (c == 0) out[b] = s * (1.0f / 16.0f);
}

// ---------------------------------------------------------------------------
// kernel_launch
// inputs: user_ids, item_ids, adj_row, adj_col, adj_val, user_emb_w, item_emb_w
// ---------------------------------------------------------------------------
extern "C" void kernel_launch(void* const* d_in, const int* in_sizes, int n_in,
                              void* d_out, int out_size) {
    const int*   uid  = (const int*)  d_in[0];
    const int*   iid  = (const int*)  d_in[1];
    const int*   rows = (const int*)  d_in[2];
    const int*   cols = (const int*)  d_in[3];
    const float* vals = (const float*)d_in[4];
    const float4* uw  = (const float4*)d_in[5];
    const float4* iw  = (const float4*)d_in[6];
    float* out = (float*)d_out;

    const int TB = 256;
    const int hi_threads   = (NNZ > N_TOTAL * 8) ? NNZ : N_TOTAL * 8;
    const int hi_blocks    = (hi_threads + TB - 1) / TB;
    const int edge_blocks  = (NNZ + TB - 1) / TB;
    const int spmm_blocks  = (N_TOTAL * 8 + TB - 1) / TB;
    const int final_blocks = (BATCH * 8 + TB - 1) / TB;

    hist_init_kernel<<<hi_blocks, TB>>>(rows, uw, iw);
    scan_local_kernel<<<NB_SCAN, SCAN_B>>>();
    scan_add2_kernel<<<NB_SCAN, SCAN_B>>>();
    scatter_kernel<<<edge_blocks, TB>>>(rows, cols, vals);

    spmm_csr_kernel<false><<<spmm_blocks, TB>>>(0, 1);   // x1 = A x0
    spmm_csr_kernel<true ><<<spmm_blocks, TB>>>(1, 2);   // x2 = A x1, s = x0+x1+x2

    final_kernel<<<final_blocks, TB>>>(uid, iid, out);
}

// round 9
// speedup vs baseline: 1.3421x; 1.3421x over previous
#include <cuda_runtime.h>
#include <cuda_fp16.h>
#include <cstdint>

#define NUM_USERS 100000
#define NUM_ITEMS 200000
#define N_TOTAL   300000
#define EMBED_DIM 64
#define NNZ       4000000
#define BATCH     16384

#define SCAN_B 1024
#define NB_SCAN ((N_TOTAL + SCAN_B - 1) / SCAN_B)   // 293

// Node features fp16: 64 halves = 8 uint4 per row. 38.4MB per buffer.
// [0]=x0, [1]=x1, [2]=x2, [3]=s = x0+x1+x2
__device__ uint4 g_xh[4][(size_t)N_TOTAL * 8];
// CSR build scratch. Zero-initialized at module load; scan_local re-zeroes
// g_cnt every replay (self-cleaning), g_cur is fully overwritten by scan_add2.
__device__ int  g_cnt[N_TOTAL];
__device__ int  g_off[N_TOTAL + 1];
__device__ int  g_cur[N_TOTAL];          // pre-biased cursor: g_cur[r] = off[r]
__device__ int  g_bsum[NB_SCAN];
// Row-sorted packed edges: (col, val_bits). 32MB.
__device__ int2 g_edges[NNZ];

// ---------------------------------------------------------------------------
// histogram over destination rows. Return value DISCARDED on purpose ->
// compiles to REDG (fire-and-forget), not ATOMG. g_cnt starts at zero.
// ---------------------------------------------------------------------------
__global__ void hist_kernel(const int* __restrict__ rows) {
    int e = blockIdx.x * blockDim.x + threadIdx.x;
    if (e >= NNZ) return;
    atomicAdd(&g_cnt[__ldg(rows + e)], 1);
}

// ---------------------------------------------------------------------------
// scan step 1: per-block inclusive scan of g_cnt, publish block sums.
// Also RESETS g_cnt to zero (self-cleaning for the next graph replay).
// ---------------------------------------------------------------------------
__global__ void scan_local_kernel() {
    __shared__ int sh[SCAN_B];
    int gid = blockIdx.x * SCAN_B + threadIdx.x;
    int v = 0;
    if (gid < N_TOTAL) {
        v = g_cnt[gid];
        g_cnt[gid] = 0;
    }
    sh[threadIdx.x] = v;
    __syncthreads();
    #pragma unroll
    for (int o = 1; o < SCAN_B; o <<= 1) {
        int t = (threadIdx.x >= o) ? sh[threadIdx.x - o] : 0;
        __syncthreads();
        sh[threadIdx.x] += t;
        __syncthreads();
    }
    if (gid < N_TOTAL) g_off[gid + 1] = sh[threadIdx.x];
    if (threadIdx.x == SCAN_B - 1) g_bsum[blockIdx.x] = sh[threadIdx.x];
}

// ---------------------------------------------------------------------------
// scan step 2: every block redundantly scans the 293 block sums in smem,
// adds its exclusive block prefix to its g_off range, AND pre-biases the
// scatter cursor: g_cur[gid] = final exclusive prefix off[gid]. The scatter
// then needs a single atomicAdd and no random g_off load.
// ---------------------------------------------------------------------------
__global__ void scan_add2_kernel() {
    __shared__ int sh[SCAN_B];
    int t = threadIdx.x;
    sh[t] = (t < NB_SCAN) ? g_bsum[t] : 0;
    __syncthreads();
    #pragma unroll
    for (int o = 1; o < SCAN_B; o <<= 1) {
        int v = (t >= o) ? sh[t - o] : 0;
        __syncthreads();
        sh[t] += v;
        __syncthreads();
    }
    int prev = (blockIdx.x > 0) ? sh[blockIdx.x - 1] : 0;

    int gid = blockIdx.x * SCAN_B + t;

    // raw local-inclusive value of element gid-1 (same block only; written by
    // scan_local). Read BEFORE the in-place += below (sync-guarded).
    int raw = 0;
    if (t > 0 && gid <= N_TOTAL) raw = g_off[gid];
    __syncthreads();

    if (gid == 0) g_off[0] = 0;
    if (gid < N_TOTAL) {
        g_off[gid + 1] += prev;
        g_cur[gid] = (t == 0) ? prev : (raw + prev);
    }
}

// ---------------------------------------------------------------------------
// scatter + init fused (the R6 winner) with the R7 cursor pre-bias:
//   idx < NNZ        : pos = atomicAdd(&g_cur[r], 1)  (single L2 round trip,
//                      no g_off load); write-back store keeps edges L2-hot
//   idx < N_TOTAL*8  : x0[idx] = fp16(concat(user_emb, item_emb))
// The DRAM-heavy init overlaps the latency-bound scatter chain.
// ---------------------------------------------------------------------------
__global__ void scatter_init_kernel(const int*   __restrict__ rows,
                                    const int*   __restrict__ cols,
                                    const float* __restrict__ vals,
                                    const float4* __restrict__ uw,
                                    const float4* __restrict__ iw) {
    int idx = blockIdx.x * blockDim.x + threadIdx.x;

    if (idx < NNZ) {
        int r = __ldg(rows + idx);
        int pos = atomicAdd(&g_cur[r], 1);
        g_edges[pos] = make_int2(__ldg(cols + idx),
                                 __float_as_int(__ldg(vals + idx)));
    }
    if (idx < N_TOTAL * 8) {
        int row = idx >> 3;
        int c   = idx & 7;
        const float4* s = (row < NUM_USERS)
            ? (uw + (size_t)row * 16 + c * 2)
            : (iw + (size_t)(row - NUM_USERS) * 16 + c * 2);
        float4 f0 = __ldg(s);
        float4 f1 = __ldg(s + 1);
        uint4 o;
        __half2* oh = reinterpret_cast<__half2*>(&o);
        oh[0] = __float22half2_rn(make_float2(f0.x, f0.y));
        oh[1] = __float22half2_rn(make_float2(f0.z, f0.w));
        oh[2] = __float22half2_rn(make_float2(f1.x, f1.y));
        oh[3] = __float22half2_rn(make_float2(f1.z, f1.w));
        g_xh[0][idx] = o;
    }
}

// ---------------------------------------------------------------------------
// fp16 CSR spmm: 8 lanes per destination row, lane c handles dims [8c,8c+8).
// 4-edge unroll for memory-level parallelism on the random gathers.
// FUSE_SUM: also write s = x0[row] + x1[row] + acc (on the x1->x2 pass)
// ---------------------------------------------------------------------------
__device__ __forceinline__ void acc8(float2& a0, float2& a1,
                                     float2& a2, float2& a3,
                                     uint4 u, float v) {
    const __half2* h = reinterpret_cast<const __half2*>(&u);
    float2 f;
    f = __half22float2(h[0]); a0.x += v * f.x; a0.y += v * f.y;
    f = __half22float2(h[1]); a1.x += v * f.x; a1.y += v * f.y;
    f = __half22float2(h[2]); a2.x += v * f.x; a2.y += v * f.y;
    f = __half22float2(h[3]); a3.x += v * f.x; a3.y += v * f.y;
}

__device__ __forceinline__ void add8(float2& a0, float2& a1,
                                     float2& a2, float2& a3, uint4 u) {
    const __half2* h = reinterpret_cast<const __half2*>(&u);
    float2 f;
    f = __half22float2(h[0]); a0.x += f.x; a0.y += f.y;
    f = __half22float2(h[1]); a1.x += f.x; a1.y += f.y;
    f = __half22float2(h[2]); a2.x += f.x; a2.y += f.y;
    f = __half22float2(h[3]); a3.x += f.x; a3.y += f.y;
}

__device__ __forceinline__ uint4 pack8(float2 a0, float2 a1,
                                       float2 a2, float2 a3) {
    uint4 o;
    __half2* oh = reinterpret_cast<__half2*>(&o);
    oh[0] = __float22half2_rn(a0);
    oh[1] = __float22half2_rn(a1);
    oh[2] = __float22half2_rn(a2);
    oh[3] = __float22half2_rn(a3);
    return o;
}

template <bool FUSE_SUM>
__global__ void spmm_csr_kernel(int src_l, int dst_l) {
    int tid = blockIdx.x * blockDim.x + threadIdx.x;
    int row = tid >> 3;
    int c   = tid & 7;
    if (row >= N_TOTAL) return;

    const uint4* __restrict__ src = g_xh[src_l];
    uint4*       __restrict__ dst = g_xh[dst_l];

    int beg = __ldg(&g_off[row]);
    int end = __ldg(&g_off[row + 1]);

    float2 a0 = {0.f, 0.f}, a1 = {0.f, 0.f}, a2 = {0.f, 0.f}, a3 = {0.f, 0.f};
    int e = beg;
    for (; e + 3 < end; e += 4) {
        int2 p0 = __ldg(&g_edges[e]);
        int2 p1 = __ldg(&g_edges[e + 1]);
        int2 p2 = __ldg(&g_edges[e + 2]);
        int2 p3 = __ldg(&g_edges[e + 3]);
        uint4 u0 = __ldg(src + ((size_t)p0.x * 8 + c));
        uint4 u1 = __ldg(src + ((size_t)p1.x * 8 + c));
        uint4 u2 = __ldg(src + ((size_t)p2.x * 8 + c));
        uint4 u3 = __ldg(src + ((size_t)p3.x * 8 + c));
        acc8(a0, a1, a2, a3, u0, __int_as_float(p0.y));
        acc8(a0, a1, a2, a3, u1, __int_as_float(p1.y));
        acc8(a0, a1, a2, a3, u2, __int_as_float(p2.y));
        acc8(a0, a1, a2, a3, u3, __int_as_float(p3.y));
    }
    for (; e < end; e++) {
        int2 p = __ldg(&g_edges[e]);
        uint4 u = __ldg(src + ((size_t)p.x * 8 + c));
        acc8(a0, a1, a2, a3, u, __int_as_float(p.y));
    }

    size_t oidx = (size_t)row * 8 + c;
    __stcs(dst + oidx, pack8(a0, a1, a2, a3));

    if (FUSE_SUM) {
        // s = x0 + x1 + x2 ; src here is x1
        add8(a0, a1, a2, a3, __ldg(&g_xh[0][oidx]));
        add8(a0, a1, a2, a3, __ldg(src + oidx));
        __stcs(&g_xh[3][oidx], pack8(a0, a1, a2, a3));
    }
}

// ---------------------------------------------------------------------------
// final: per batch element, compute layer-3 rows u and i on the fly from x2,
// add s, dot, scale. 8 lanes per batch element; lane c owns dims [8c, 8c+8).
// ---------------------------------------------------------------------------
__global__ void final_kernel(const int* __restrict__ uid,
                             const int* __restrict__ iid,
                             float* __restrict__ out) {
    int tid = blockIdx.x * blockDim.x + threadIdx.x;
    if (tid >= BATCH * 8) return;
    int b = tid >> 3;
    int c = tid & 7;

    int ru = __ldg(uid + b);
    int ri = __ldg(iid + b) + NUM_USERS;

    const uint4* __restrict__ x2 = g_xh[2];

    float fu[8], fi[8];
    {   // s rows
        uint4 su = __ldg(&g_xh[3][(size_t)ru * 8 + c]);
        uint4 si = __ldg(&g_xh[3][(size_t)ri * 8 + c]);
        const __half2* hu = reinterpret_cast<const __half2*>(&su);
        const __half2* hi = reinterpret_cast<const __half2*>(&si);
        #pragma unroll
        for (int k = 0; k < 4; k++) {
            float2 f = __half22float2(hu[k]);
            fu[2 * k] = f.x; fu[2 * k + 1] = f.y;
            f = __half22float2(hi[k]);
            fi[2 * k] = f.x; fi[2 * k + 1] = f.y;
        }
    }

    // layer-3 row u
    {
        int beg = __ldg(&g_off[ru]);
        int end = __ldg(&g_off[ru + 1]);
        for (int e = beg; e < end; e++) {
            int2 p = __ldg(&g_edges[e]);
            uint4 u = __ldg(x2 + ((size_t)p.x * 8 + c));
            float v = __int_as_float(p.y);
            const __half2* h = reinterpret_cast<const __half2*>(&u);
            #pragma unroll
            for (int k = 0; k < 4; k++) {
                float2 f = __half22float2(h[k]);
                fu[2 * k]     += v * f.x;
                fu[2 * k + 1] += v * f.y;
            }
        }
    }
    // layer-3 row i
    {
        int beg = __ldg(&g_off[ri]);
        int end = __ldg(&g_off[ri + 1]);
        for (int e = beg; e < end; e++) {
            int2 p = __ldg(&g_edges[e]);
            uint4 u = __ldg(x2 + ((size_t)p.x * 8 + c));
            float v = __int_as_float(p.y);
            const __half2* h = reinterpret_cast<const __half2*>(&u);
            #pragma unroll
            for (int k = 0; k < 4; k++) {
                float2 f = __half22float2(h[k]);
                fi[2 * k]     += v * f.x;
                fi[2 * k + 1] += v * f.y;
            }
        }
    }

    float s = 0.f;
    #pragma unroll
    for (int k = 0; k < 8; k++) s += fu[k] * fi[k];

    #pragma unroll
    for (int o = 4; o > 0; o >>= 1)
        s += __shfl_down_sync(0xffffffffu, s, o, 8);

    if (c == 0) out[b] = s * (1.0f / 16.0f);
}

// ---------------------------------------------------------------------------
// kernel_launch
// inputs: user_ids, item_ids, adj_row, adj_col, adj_val, user_emb_w, item_emb_w
// ---------------------------------------------------------------------------
extern "C" void kernel_launch(void* const* d_in, const int* in_sizes, int n_in,
                              void* d_out, int out_size) {
    const int*   uid  = (const int*)  d_in[0];
    const int*   iid  = (const int*)  d_in[1];
    const int*   rows = (const int*)  d_in[2];
    const int*   cols = (const int*)  d_in[3];
    const float* vals = (const float*)d_in[4];
    const float4* uw  = (const float4*)d_in[5];
    const float4* iw  = (const float4*)d_in[6];
    float* out = (float*)d_out;

    const int TB = 256;
    const int edge_blocks  = (NNZ + TB - 1) / TB;
    const int si_threads   = (NNZ > N_TOTAL * 8) ? NNZ : N_TOTAL * 8;
    const int si_blocks    = (si_threads + TB - 1) / TB;
    const int spmm_blocks  = (N_TOTAL * 8 + TB - 1) / TB;
    const int final_blocks = (BATCH * 8 + TB - 1) / TB;

    hist_kernel<<<edge_blocks, TB>>>(rows);
    scan_local_kernel<<<NB_SCAN, SCAN_B>>>();
    scan_add2_kernel<<<NB_SCAN, SCAN_B>>>();
    scatter_init_kernel<<<si_blocks, TB>>>(rows, cols, vals, uw, iw);

    spmm_csr_kernel<false><<<spmm_blocks, TB>>>(0, 1);   // x1 = A x0
    spmm_csr_kernel<true ><<<spmm_blocks, TB>>>(1, 2);   // x2 = A x1, s = x0+x1+x2

    final_kernel<<<final_blocks, TB>>>(uid, iid, out);
}

// round 10
// speedup vs baseline: 1.4215x; 1.0592x over previous
#include <cuda_runtime.h>
#include <cuda_fp16.h>
#include <cstdint>

#define NUM_USERS 100000
#define NUM_ITEMS 200000
#define N_TOTAL   300000
#define EMBED_DIM 64
#define NNZ       4000000
#define BATCH     16384

#define SCAN_B 1024
#define NB_SCAN ((N_TOTAL + SCAN_B - 1) / SCAN_B)   // 293

// Node features fp16: 64 halves = 8 uint4 per row. 38.4MB per buffer.
// [0]=x0, [1]=x1, [2]=x2   (the layer-sum is formed at queried rows in final)
__device__ uint4 g_xh[3][(size_t)N_TOTAL * 8];
// CSR build scratch. Zero-initialized at module load; scan_local re-zeroes
// g_cnt every replay (self-cleaning), g_cur is fully overwritten by scan_add2.
__device__ int  g_cnt[N_TOTAL];
__device__ int  g_off[N_TOTAL + 1];
__device__ int  g_cur[N_TOTAL];          // pre-biased cursor: g_cur[r] = off[r]
__device__ int  g_bsum[NB_SCAN];
// Row-sorted packed edges: (col, val_bits). 32MB.
__device__ int2 g_edges[NNZ];

// ---------------------------------------------------------------------------
// Side stream + fork/join events, created ONCE at module load (before the
// harness's memory checkpoints and before any graph capture). Used to run
// the x0 init concurrently with the CSR build chain.
// ---------------------------------------------------------------------------
struct SideStream {
    cudaStream_t s;
    cudaEvent_t  fork, join;
    SideStream() {
        cudaStreamCreateWithFlags(&s, cudaStreamNonBlocking);
        cudaEventCreateWithFlags(&fork, cudaEventDisableTiming);
        cudaEventCreateWithFlags(&join, cudaEventDisableTiming);
    }
};
static SideStream g_ss;

// ---------------------------------------------------------------------------
// init: x0 = fp16(concat(user_emb, item_emb)). Runs on the side stream.
// ---------------------------------------------------------------------------
__global__ void init_kernel(const float4* __restrict__ uw,
                            const float4* __restrict__ iw) {
    int idx = blockIdx.x * blockDim.x + threadIdx.x;
    if (idx >= N_TOTAL * 8) return;
    int row = idx >> 3;
    int c   = idx & 7;
    const float4* s = (row < NUM_USERS)
        ? (uw + (size_t)row * 16 + c * 2)
        : (iw + (size_t)(row - NUM_USERS) * 16 + c * 2);
    float4 f0 = __ldg(s);
    float4 f1 = __ldg(s + 1);
    uint4 o;
    __half2* oh = reinterpret_cast<__half2*>(&o);
    oh[0] = __float22half2_rn(make_float2(f0.x, f0.y));
    oh[1] = __float22half2_rn(make_float2(f0.z, f0.w));
    oh[2] = __float22half2_rn(make_float2(f1.x, f1.y));
    oh[3] = __float22half2_rn(make_float2(f1.z, f1.w));
    g_xh[0][idx] = o;
}

// ---------------------------------------------------------------------------
// histogram over destination rows. Return value DISCARDED on purpose ->
// compiles to REDG (fire-and-forget), not ATOMG. g_cnt starts at zero.
// ---------------------------------------------------------------------------
__global__ void hist_kernel(const int* __restrict__ rows) {
    int e = blockIdx.x * blockDim.x + threadIdx.x;
    if (e >= NNZ) return;
    atomicAdd(&g_cnt[__ldg(rows + e)], 1);
}

// ---------------------------------------------------------------------------
// scan step 1: per-block inclusive scan of g_cnt, publish block sums.
// Also RESETS g_cnt to zero (self-cleaning for the next graph replay).
// ---------------------------------------------------------------------------
__global__ void scan_local_kernel() {
    __shared__ int sh[SCAN_B];
    int gid = blockIdx.x * SCAN_B + threadIdx.x;
    int v = 0;
    if (gid < N_TOTAL) {
        v = g_cnt[gid];
        g_cnt[gid] = 0;
    }
    sh[threadIdx.x] = v;
    __syncthreads();
    #pragma unroll
    for (int o = 1; o < SCAN_B; o <<= 1) {
        int t = (threadIdx.x >= o) ? sh[threadIdx.x - o] : 0;
        __syncthreads();
        sh[threadIdx.x] += t;
        __syncthreads();
    }
    if (gid < N_TOTAL) g_off[gid + 1] = sh[threadIdx.x];
    if (threadIdx.x == SCAN_B - 1) g_bsum[blockIdx.x] = sh[threadIdx.x];
}

// ---------------------------------------------------------------------------
// scan step 2: every block redundantly scans the 293 block sums in smem,
// adds its exclusive block prefix to its g_off range, AND pre-biases the
// scatter cursor: g_cur[gid] = final exclusive prefix off[gid].
// ---------------------------------------------------------------------------
__global__ void scan_add2_kernel() {
    __shared__ int sh[SCAN_B];
    int t = threadIdx.x;
    sh[t] = (t < NB_SCAN) ? g_bsum[t] : 0;
    __syncthreads();
    #pragma unroll
    for (int o = 1; o < SCAN_B; o <<= 1) {
        int v = (t >= o) ? sh[t - o] : 0;
        __syncthreads();
        sh[t] += v;
        __syncthreads();
    }
    int prev = (blockIdx.x > 0) ? sh[blockIdx.x - 1] : 0;

    int gid = blockIdx.x * SCAN_B + t;

    // raw local-inclusive value of element gid-1 (same block only; written by
    // scan_local). Read BEFORE the in-place += below (sync-guarded).
    int raw = 0;
    if (t > 0 && gid <= N_TOTAL) raw = g_off[gid];
    __syncthreads();

    if (gid == 0) g_off[0] = 0;
    if (gid < N_TOTAL) {
        g_off[gid + 1] += prev;
        g_cur[gid] = (t == 0) ? prev : (raw + prev);
    }
}

// ---------------------------------------------------------------------------
// scatter: 2 edges per thread (independent ATOMG chains -> 2x MLP on the
// latency-bound cursor atomic). Single pre-biased atomic per edge, no g_off
// load. Write-back stores keep edges L2-resident for spmm1.
// ---------------------------------------------------------------------------
__global__ void scatter_kernel(const int*   __restrict__ rows,
                               const int*   __restrict__ cols,
                               const float* __restrict__ vals) {
    int t = blockIdx.x * blockDim.x + threadIdx.x;
    int e0 = t * 2;
    if (e0 >= NNZ) return;   // NNZ is even, no partial pair

    int2   r2 = __ldg((const int2*)  (rows + e0));
    int2   c2 = __ldg((const int2*)  (cols + e0));
    float2 v2 = __ldg((const float2*)(vals + e0));

    int pos0 = atomicAdd(&g_cur[r2.x], 1);
    int pos1 = atomicAdd(&g_cur[r2.y], 1);
    g_edges[pos0] = make_int2(c2.x, __float_as_int(v2.x));
    g_edges[pos1] = make_int2(c2.y, __float_as_int(v2.y));
}

// ---------------------------------------------------------------------------
// fp16 CSR spmm: 8 lanes per destination row, lane c handles dims [8c,8c+8).
// 4-edge unroll for memory-level parallelism on the random gathers.
// ---------------------------------------------------------------------------
__device__ __forceinline__ void acc8(float2& a0, float2& a1,
                                     float2& a2, float2& a3,
                                     uint4 u, float v) {
    const __half2* h = reinterpret_cast<const __half2*>(&u);
    float2 f;
    f = __half22float2(h[0]); a0.x += v * f.x; a0.y += v * f.y;
    f = __half22float2(h[1]); a1.x += v * f.x; a1.y += v * f.y;
    f = __half22float2(h[2]); a2.x += v * f.x; a2.y += v * f.y;
    f = __half22float2(h[3]); a3.x += v * f.x; a3.y += v * f.y;
}

__device__ __forceinline__ uint4 pack8(float2 a0, float2 a1,
                                       float2 a2, float2 a3) {
    uint4 o;
    __half2* oh = reinterpret_cast<__half2*>(&o);
    oh[0] = __float22half2_rn(a0);
    oh[1] = __float22half2_rn(a1);
    oh[2] = __float22half2_rn(a2);
    oh[3] = __float22half2_rn(a3);
    return o;
}

__global__ void spmm_csr_kernel(int src_l, int dst_l) {
    int tid = blockIdx.x * blockDim.x + threadIdx.x;
    int row = tid >> 3;
    int c   = tid & 7;
    if (row >= N_TOTAL) return;

    const uint4* __restrict__ src = g_xh[src_l];
    uint4*       __restrict__ dst = g_xh[dst_l];

    int beg = __ldg(&g_off[row]);
    int end = __ldg(&g_off[row + 1]);

    float2 a0 = {0.f, 0.f}, a1 = {0.f, 0.f}, a2 = {0.f, 0.f}, a3 = {0.f, 0.f};
    int e = beg;
    for (; e + 3 < end; e += 4) {
        int2 p0 = __ldg(&g_edges[e]);
        int2 p1 = __ldg(&g_edges[e + 1]);
        int2 p2 = __ldg(&g_edges[e + 2]);
        int2 p3 = __ldg(&g_edges[e + 3]);
        uint4 u0 = __ldg(src + ((size_t)p0.x * 8 + c));
        uint4 u1 = __ldg(src + ((size_t)p1.x * 8 + c));
        uint4 u2 = __ldg(src + ((size_t)p2.x * 8 + c));
        uint4 u3 = __ldg(src + ((size_t)p3.x * 8 + c));
        acc8(a0, a1, a2, a3, u0, __int_as_float(p0.y));
        acc8(a0, a1, a2, a3, u1, __int_as_float(p1.y));
        acc8(a0, a1, a2, a3, u2, __int_as_float(p2.y));
        acc8(a0, a1, a2, a3, u3, __int_as_float(p3.y));
    }
    for (; e < end; e++) {
        int2 p = __ldg(&g_edges[e]);
        uint4 u = __ldg(src + ((size_t)p.x * 8 + c));
        acc8(a0, a1, a2, a3, u, __int_as_float(p.y));
    }

    __stcs(dst + ((size_t)row * 8 + c), pack8(a0, a1, a2, a3));
}

// ---------------------------------------------------------------------------
// final: per batch element, s = x0+x1+x2 at rows u,i plus layer-3 computed
// on the fly from x2; dot, scale. 8 lanes per batch element.
// ---------------------------------------------------------------------------
__device__ __forceinline__ void sum_row(float* f, size_t idx) {
    f[0]=f[1]=f[2]=f[3]=f[4]=f[5]=f[6]=f[7]=0.f;
    #pragma unroll
    for (int l = 0; l < 3; l++) {
        uint4 x = __ldg(&g_xh[l][idx]);
        const __half2* h = reinterpret_cast<const __half2*>(&x);
        #pragma unroll
        for (int k = 0; k < 4; k++) {
            float2 ff = __half22float2(h[k]);
            f[2 * k]     += ff.x;
            f[2 * k + 1] += ff.y;
        }
    }
}

__global__ void final_kernel(const int* __restrict__ uid,
                             const int* __restrict__ iid,
                             float* __restrict__ out) {
    int tid = blockIdx.x * blockDim.x + threadIdx.x;
    if (tid >= BATCH * 8) return;
    int b = tid >> 3;
    int c = tid & 7;

    int ru = __ldg(uid + b);
    int ri = __ldg(iid + b) + NUM_USERS;

    const uint4* __restrict__ x2 = g_xh[2];

    float fu[8], fi[8];
    sum_row(fu, (size_t)ru * 8 + c);
    sum_row(fi, (size_t)ri * 8 + c);

    // layer-3 row u
    {
        int beg = __ldg(&g_off[ru]);
        int end = __ldg(&g_off[ru + 1]);
        for (int e = beg; e < end; e++) {
            int2 p = __ldg(&g_edges[e]);
            uint4 u = __ldg(x2 + ((size_t)p.x * 8 + c));
            float v = __int_as_float(p.y);
            const __half2* h = reinterpret_cast<const __half2*>(&u);
            #pragma unroll
            for (int k = 0; k < 4; k++) {
                float2 f = __half22float2(h[k]);
                fu[2 * k]     += v * f.x;
                fu[2 * k + 1] += v * f.y;
            }
        }
    }
    // layer-3 row i
    {
        int beg = __ldg(&g_off[ri]);
        int end = __ldg(&g_off[ri + 1]);
        for (int e = beg; e < end; e++) {
            int2 p = __ldg(&g_edges[e]);
            uint4 u = __ldg(x2 + ((size_t)p.x * 8 + c));
            float v = __int_as_float(p.y);
            const __half2* h = reinterpret_cast<const __half2*>(&u);
            #pragma unroll
            for (int k = 0; k < 4; k++) {
                float2 f = __half22float2(h[k]);
                fi[2 * k]     += v * f.x;
                fi[2 * k + 1] += v * f.y;
            }
        }
    }

    float s = 0.f;
    #pragma unroll
    for (int k = 0; k < 8; k++) s += fu[k] * fi[k];

    #pragma unroll
    for (int o = 4; o > 0; o >>= 1)
        s += __shfl_down_sync(0xffffffffu, s, o, 8);

    if (c == 0) out[b] = s * (1.0f / 16.0f);
}

// ---------------------------------------------------------------------------
// kernel_launch
// inputs: user_ids, item_ids, adj_row, adj_col, adj_val, user_emb_w, item_emb_w
// Fork: init runs on the side stream concurrently with the CSR build chain;
// joined before spmm1 (which is the first consumer of x0).
// ---------------------------------------------------------------------------
extern "C" void kernel_launch(void* const* d_in, const int* in_sizes, int n_in,
                              void* d_out, int out_size) {
    const int*   uid  = (const int*)  d_in[0];
    const int*   iid  = (const int*)  d_in[1];
    const int*   rows = (const int*)  d_in[2];
    const int*   cols = (const int*)  d_in[3];
    const float* vals = (const float*)d_in[4];
    const float4* uw  = (const float4*)d_in[5];
    const float4* iw  = (const float4*)d_in[6];
    float* out = (float*)d_out;

    const int TB = 256;
    const int init_blocks   = (N_TOTAL * 8 + TB - 1) / TB;
    const int edge_blocks   = (NNZ + TB - 1) / TB;
    const int scat_blocks   = (NNZ / 2 + TB - 1) / TB;
    const int spmm_blocks   = (N_TOTAL * 8 + TB - 1) / TB;
    const int final_blocks  = (BATCH * 8 + TB - 1) / TB;

    // fork: x0 init on side stream (independent of the CSR build)
    cudaEventRecord(g_ss.fork, 0);
    cudaStreamWaitEvent(g_ss.s, g_ss.fork, 0);
    init_kernel<<<init_blocks, TB, 0, g_ss.s>>>(uw, iw);
    cudaEventRecord(g_ss.join, g_ss.s);

    // CSR build chain on the main stream
    hist_kernel<<<edge_blocks, TB>>>(rows);
    scan_local_kernel<<<NB_SCAN, SCAN_B>>>();
    scan_add2_kernel<<<NB_SCAN, SCAN_B>>>();
    scatter_kernel<<<scat_blocks, TB>>>(rows, cols, vals);

    // join: spmm1 needs x0
    cudaStreamWaitEvent(0, g_ss.join, 0);

    spmm_csr_kernel<<<spmm_blocks, TB>>>(0, 1);   // x1 = A x0
    spmm_csr_kernel<<<spmm_blocks, TB>>>(1, 2);   // x2 = A x1

    final_kernel<<<final_blocks, TB>>>(uid, iid, out);
}

// round 11
// speedup vs baseline: 1.4297x; 1.0057x over previous
#include <cuda_runtime.h>
#include <cuda_fp16.h>
#include <cstdint>

#define NUM_USERS 100000
#define NUM_ITEMS 200000
#define N_TOTAL   300000
#define EMBED_DIM 64
#define NNZ       4000000
#define BATCH     16384

#define SCAN_B 1024
#define NB_SCAN ((N_TOTAL + SCAN_B - 1) / SCAN_B)   // 293

// Node features fp16: 64 halves = 8 uint4 per row. 38.4MB per buffer.
// [0]=x0, [1]=x1, [2]=x2   (the layer-sum is formed at queried rows in final)
__device__ uint4 g_xh[3][(size_t)N_TOTAL * 8];
// CSR build scratch. Zero-initialized at module load; every kernel leaves its
// scratch zeroed again for the next graph replay (self-cleaning).
__device__ int  g_cnt[N_TOTAL];
__device__ int  g_off[N_TOTAL + 1];
__device__ int  g_cur[N_TOTAL];          // pre-biased cursor: g_cur[r] = off[r]
// Decoupled-lookback state: status (hi 32) | value (lo 32). 0 = invalid,
// 1 = aggregate, 2 = inclusive prefix. Reset to 0 by scatter_kernel.
__device__ unsigned long long g_look[NB_SCAN];
// Row-sorted packed edges: (col, val_bits). 32MB.
__device__ int2 g_edges[NNZ];

// ---------------------------------------------------------------------------
// Side stream + fork/join events, created ONCE at module load (before the
// harness's memory checkpoints and before any graph capture).
// ---------------------------------------------------------------------------
struct SideStream {
    cudaStream_t s;
    cudaEvent_t  fork, join;
    SideStream() {
        cudaStreamCreateWithFlags(&s, cudaStreamNonBlocking);
        cudaEventCreateWithFlags(&fork, cudaEventDisableTiming);
        cudaEventCreateWithFlags(&join, cudaEventDisableTiming);
    }
};
static SideStream g_ss;

// ---------------------------------------------------------------------------
// init: x0 = fp16(concat(user_emb, item_emb)). Runs on the side stream,
// overlapped with the CSR build chain.
// ---------------------------------------------------------------------------
__global__ void init_kernel(const float4* __restrict__ uw,
                            const float4* __restrict__ iw) {
    int idx = blockIdx.x * blockDim.x + threadIdx.x;
    if (idx >= N_TOTAL * 8) return;
    int row = idx >> 3;
    int c   = idx & 7;
    const float4* s = (row < NUM_USERS)
        ? (uw + (size_t)row * 16 + c * 2)
        : (iw + (size_t)(row - NUM_USERS) * 16 + c * 2);
    float4 f0 = __ldg(s);
    float4 f1 = __ldg(s + 1);
    uint4 o;
    __half2* oh = reinterpret_cast<__half2*>(&o);
    oh[0] = __float22half2_rn(make_float2(f0.x, f0.y));
    oh[1] = __float22half2_rn(make_float2(f0.z, f0.w));
    oh[2] = __float22half2_rn(make_float2(f1.x, f1.y));
    oh[3] = __float22half2_rn(make_float2(f1.z, f1.w));
    g_xh[0][idx] = o;
}

// ---------------------------------------------------------------------------
// histogram: 4 edges/thread (int4 load, 4 independent REDG chains).
// Return values DISCARDED -> REDG fire-and-forget. g_cnt starts at zero.
// ---------------------------------------------------------------------------
__global__ void hist_kernel(const int4* __restrict__ rows4) {
    int t = blockIdx.x * blockDim.x + threadIdx.x;
    if (t >= NNZ / 4) return;
    int4 r = __ldg(rows4 + t);
    atomicAdd(&g_cnt[r.x], 1);
    atomicAdd(&g_cnt[r.y], 1);
    atomicAdd(&g_cnt[r.z], 1);
    atomicAdd(&g_cnt[r.w], 1);
}

// ---------------------------------------------------------------------------
// Single-pass scan with decoupled lookback (CUB-style).
// Per block: local inclusive scan of its 1024 counts (resetting g_cnt),
// publish aggregate, warp-0 lookback to compute the exclusive block prefix,
// publish inclusive prefix, then write g_off and the pre-biased g_cur.
// All 293 blocks are co-resident (1024 thr/block, 2 blocks/SM x 148 SMs).
// ---------------------------------------------------------------------------
__global__ void scan_kernel() {
    __shared__ int sh[SCAN_B];
    __shared__ int s_prefix;
    int t   = threadIdx.x;
    int bid = blockIdx.x;
    int gid = bid * SCAN_B + t;

    int v = 0;
    if (gid < N_TOTAL) {
        v = g_cnt[gid];
        g_cnt[gid] = 0;
    }
    sh[t] = v;
    __syncthreads();
    #pragma unroll
    for (int o = 1; o < SCAN_B; o <<= 1) {
        int x = (t >= o) ? sh[t - o] : 0;
        __syncthreads();
        sh[t] += x;
        __syncthreads();
    }
    int total = sh[SCAN_B - 1];

    // publish: block 0 publishes its inclusive prefix directly
    if (t == 0) {
        unsigned long long pack =
            (((unsigned long long)(bid == 0 ? 2u : 1u)) << 32) |
            (unsigned int)total;
        atomicExch(&g_look[bid], pack);
    }

    // warp 0: lookback over predecessors
    if (t < 32) {
        int prefix = 0;
        if (bid > 0) {
            int base = bid - 1;
            while (true) {
                int idx = base - t;
                unsigned long long pk = 0;
                if (idx >= 0) {
                    do {
                        pk = atomicAdd(&g_look[idx], 0ull);   // atomic read
                    } while ((pk >> 32) == 0ull);
                }
                unsigned st  = (idx >= 0) ? (unsigned)(pk >> 32) : 2u;
                int      val = (idx >= 0) ? (int)(unsigned)pk : 0;
                unsigned pmask = __ballot_sync(0xffffffffu, st == 2u);
                if (pmask) {
                    int firstp  = __ffs(pmask) - 1;   // closest prefix lane
                    int contrib = (t <= firstp) ? val : 0;
                    #pragma unroll
                    for (int o = 16; o > 0; o >>= 1)
                        contrib += __shfl_down_sync(0xffffffffu, contrib, o);
                    if (t == 0) prefix += contrib;
                    break;
                } else {
                    int contrib = val;
                    #pragma unroll
                    for (int o = 16; o > 0; o >>= 1)
                        contrib += __shfl_down_sync(0xffffffffu, contrib, o);
                    if (t == 0) prefix += contrib;
                    base -= 32;
                }
            }
            if (t == 0) {
                unsigned long long pack =
                    (2ull << 32) | (unsigned int)(prefix + total);
                atomicExch(&g_look[bid], pack);
            }
        }
        if (t == 0) s_prefix = prefix;
    }
    __syncthreads();
    int prefix = s_prefix;

    if (gid == 0) g_off[0] = 0;
    if (gid < N_TOTAL) {
        int incl = prefix + sh[t];
        g_off[gid + 1] = incl;
        g_cur[gid]     = incl - v;   // exclusive prefix = pre-biased cursor
    }
}

// ---------------------------------------------------------------------------
// scatter: 4 edges/thread (4 independent ATOMG chains). Single pre-biased
// atomic per edge, no g_off load. Write-back stores keep edges L2-resident
// for spmm1. Also resets the lookback flags for the next replay.
// ---------------------------------------------------------------------------
__global__ void scatter_kernel(const int4*   __restrict__ rows4,
                               const int4*   __restrict__ cols4,
                               const float4* __restrict__ vals4) {
    int t = blockIdx.x * blockDim.x + threadIdx.x;

    // reset lookback state (scan_kernel fully retired by stream order)
    if (blockIdx.x == 0) {
        for (int i = threadIdx.x; i < NB_SCAN; i += blockDim.x)
            g_look[i] = 0ull;
    }

    if (t >= NNZ / 4) return;
    int4   r = __ldg(rows4 + t);
    int4   c = __ldg(cols4 + t);
    float4 v = __ldg(vals4 + t);

    int p0 = atomicAdd(&g_cur[r.x], 1);
    int p1 = atomicAdd(&g_cur[r.y], 1);
    int p2 = atomicAdd(&g_cur[r.z], 1);
    int p3 = atomicAdd(&g_cur[r.w], 1);
    g_edges[p0] = make_int2(c.x, __float_as_int(v.x));
    g_edges[p1] = make_int2(c.y, __float_as_int(v.y));
    g_edges[p2] = make_int2(c.z, __float_as_int(v.z));
    g_edges[p3] = make_int2(c.w, __float_as_int(v.w));
}

// ---------------------------------------------------------------------------
// fp16 CSR spmm: 8 lanes per destination row, lane c handles dims [8c,8c+8).
// 4-edge unroll for memory-level parallelism on the random gathers.
// ---------------------------------------------------------------------------
__device__ __forceinline__ void acc8(float2& a0, float2& a1,
                                     float2& a2, float2& a3,
                                     uint4 u, float v) {
    const __half2* h = reinterpret_cast<const __half2*>(&u);
    float2 f;
    f = __half22float2(h[0]); a0.x += v * f.x; a0.y += v * f.y;
    f = __half22float2(h[1]); a1.x += v * f.x; a1.y += v * f.y;
    f = __half22float2(h[2]); a2.x += v * f.x; a2.y += v * f.y;
    f = __half22float2(h[3]); a3.x += v * f.x; a3.y += v * f.y;
}

__device__ __forceinline__ uint4 pack8(float2 a0, float2 a1,
                                       float2 a2, float2 a3) {
    uint4 o;
    __half2* oh = reinterpret_cast<__half2*>(&o);
    oh[0] = __float22half2_rn(a0);
    oh[1] = __float22half2_rn(a1);
    oh[2] = __float22half2_rn(a2);
    oh[3] = __float22half2_rn(a3);
    return o;
}

__global__ void spmm_csr_kernel(int src_l, int dst_l) {
    int tid = blockIdx.x * blockDim.x + threadIdx.x;
    int row = tid >> 3;
    int c   = tid & 7;
    if (row >= N_TOTAL) return;

    const uint4* __restrict__ src = g_xh[src_l];
    uint4*       __restrict__ dst = g_xh[dst_l];

    int beg = __ldg(&g_off[row]);
    int end = __ldg(&g_off[row + 1]);

    float2 a0 = {0.f, 0.f}, a1 = {0.f, 0.f}, a2 = {0.f, 0.f}, a3 = {0.f, 0.f};
    int e = beg;
    for (; e + 3 < end; e += 4) {
        int2 p0 = __ldg(&g_edges[e]);
        int2 p1 = __ldg(&g_edges[e + 1]);
        int2 p2 = __ldg(&g_edges[e + 2]);
        int2 p3 = __ldg(&g_edges[e + 3]);
        uint4 u0 = __ldg(src + ((size_t)p0.x * 8 + c));
        uint4 u1 = __ldg(src + ((size_t)p1.x * 8 + c));
        uint4 u2 = __ldg(src + ((size_t)p2.x * 8 + c));
        uint4 u3 = __ldg(src + ((size_t)p3.x * 8 + c));
        acc8(a0, a1, a2, a3, u0, __int_as_float(p0.y));
        acc8(a0, a1, a2, a3, u1, __int_as_float(p1.y));
        acc8(a0, a1, a2, a3, u2, __int_as_float(p2.y));
        acc8(a0, a1, a2, a3, u3, __int_as_float(p3.y));
    }
    for (; e < end; e++) {
        int2 p = __ldg(&g_edges[e]);
        uint4 u = __ldg(src + ((size_t)p.x * 8 + c));
        acc8(a0, a1, a2, a3, u, __int_as_float(p.y));
    }

    __stcs(dst + ((size_t)row * 8 + c), pack8(a0, a1, a2, a3));
}

// ---------------------------------------------------------------------------
// final: per batch element, s = x0+x1+x2 at rows u,i plus layer-3 computed
// on the fly from x2; dot, scale. 8 lanes per batch element.
// ---------------------------------------------------------------------------
__device__ __forceinline__ void sum_row(float* f, size_t idx) {
    f[0]=f[1]=f[2]=f[3]=f[4]=f[5]=f[6]=f[7]=0.f;
    #pragma unroll
    for (int l = 0; l < 3; l++) {
        uint4 x = __ldg(&g_xh[l][idx]);
        const __half2* h = reinterpret_cast<const __half2*>(&x);
        #pragma unroll
        for (int k = 0; k < 4; k++) {
            float2 ff = __half22float2(h[k]);
            f[2 * k]     += ff.x;
            f[2 * k + 1] += ff.y;
        }
    }
}

__global__ void final_kernel(const int* __restrict__ uid,
                             const int* __restrict__ iid,
                             float* __restrict__ out) {
    int tid = blockIdx.x * blockDim.x + threadIdx.x;
    if (tid >= BATCH * 8) return;
    int b = tid >> 3;
    int c = tid & 7;

    int ru = __ldg(uid + b);
    int ri = __ldg(iid + b) + NUM_USERS;

    const uint4* __restrict__ x2 = g_xh[2];

    float fu[8], fi[8];
    sum_row(fu, (size_t)ru * 8 + c);
    sum_row(fi, (size_t)ri * 8 + c);

    {   // layer-3 row u
        int beg = __ldg(&g_off[ru]);
        int end = __ldg(&g_off[ru + 1]);
        for (int e = beg; e < end; e++) {
            int2 p = __ldg(&g_edges[e]);
            uint4 u = __ldg(x2 + ((size_t)p.x * 8 + c));
            float v = __int_as_float(p.y);
            const __half2* h = reinterpret_cast<const __half2*>(&u);
            #pragma unroll
            for (int k = 0; k < 4; k++) {
                float2 f = __half22float2(h[k]);
                fu[2 * k]     += v * f.x;
                fu[2 * k + 1] += v * f.y;
            }
        }
    }
    {   // layer-3 row i
        int beg = __ldg(&g_off[ri]);
        int end = __ldg(&g_off[ri + 1]);
        for (int e = beg; e < end; e++) {
            int2 p = __ldg(&g_edges[e]);
            uint4 u = __ldg(x2 + ((size_t)p.x * 8 + c));
            float v = __int_as_float(p.y);
            const __half2* h = reinterpret_cast<const __half2*>(&u);
            #pragma unroll
            for (int k = 0; k < 4; k++) {
                float2 f = __half22float2(h[k]);
                fi[2 * k]     += v * f.x;
                fi[2 * k + 1] += v * f.y;
            }
        }
    }

    float s = 0.f;
    #pragma unroll
    for (int k = 0; k < 8; k++) s += fu[k] * fi[k];

    #pragma unroll
    for (int o = 4; o > 0; o >>= 1)
        s += __shfl_down_sync(0xffffffffu, s, o, 8);

    if (c == 0) out[b] = s * (1.0f / 16.0f);
}

// ---------------------------------------------------------------------------
// kernel_launch
// inputs: user_ids, item_ids, adj_row, adj_col, adj_val, user_emb_w, item_emb_w
// ---------------------------------------------------------------------------
extern "C" void kernel_launch(void* const* d_in, const int* in_sizes, int n_in,
                              void* d_out, int out_size) {
    const int*   uid  = (const int*)  d_in[0];
    const int*   iid  = (const int*)  d_in[1];
    const int4*  rows4 = (const int4*)  d_in[2];
    const int4*  cols4 = (const int4*)  d_in[3];
    const float4* vals4 = (const float4*)d_in[4];
    const float4* uw  = (const float4*)d_in[5];
    const float4* iw  = (const float4*)d_in[6];
    float* out = (float*)d_out;

    const int TB = 256;
    const int init_blocks  = (N_TOTAL * 8 + TB - 1) / TB;
    const int e4_blocks    = (NNZ / 4 + TB - 1) / TB;
    const int spmm_blocks  = (N_TOTAL * 8 + TB - 1) / TB;
    const int final_blocks = (BATCH * 8 + TB - 1) / TB;

    // fork: x0 init on side stream (independent of the CSR build)
    cudaEventRecord(g_ss.fork, 0);
    cudaStreamWaitEvent(g_ss.s, g_ss.fork, 0);
    init_kernel<<<init_blocks, TB, 0, g_ss.s>>>(uw, iw);
    cudaEventRecord(g_ss.join, g_ss.s);

    // CSR build chain on the main stream
    hist_kernel<<<e4_blocks, TB>>>(rows4);
    scan_kernel<<<NB_SCAN, SCAN_B>>>();
    scatter_kernel<<<e4_blocks, TB>>>(rows4, cols4, vals4);

    // join: spmm1 needs x0
    cudaStreamWaitEvent(0, g_ss.join, 0);

    spmm_csr_kernel<<<spmm_blocks, TB>>>(0, 1);   // x1 = A x0
    spmm_csr_kernel<<<spmm_blocks, TB>>>(1, 2);   // x2 = A x1

    final_kernel<<<final_blocks, TB>>>(uid, iid, out);
}